// round 15
// baseline (speedup 1.0000x reference)
#include <cuda_runtime.h>

#define H       1536
#define NH      12
#define NKV     2
#define GQA     6
#define HD      128
#define CTX     4096
#define NLAYERS 28
#define NSPLIT  128
#define NBLK    256      // 2 CTAs/SM * 148 = 296 >= 256 -> co-resident
#define NTHR    512

// smem float offsets
#define OFF_WA  0        // 12288 floats (8 qkv rows: 0-3 cp.async, 4-7 bulk)
#define OFF_WO  12288    // 9216 floats (6 oproj rows: 0-2 cp.async, 3-5 bulk)
#define OFF_NC  21504    // 1536 floats (norm vec / ctx)
#define OFF_KB  23040    // 2048 floats (16 warps x 128 K)
#define OFF_VB  25088    // 2048 floats (16 warps x 128 V)
#define SMEM_FLOATS 27136   // 108544 bytes

// ---------------- device globals (zero-init; counters self-reset) --------------
__device__ __align__(16) float g_qkv[2048];   // q:0..1535, k:1536..1791, v:1792..2047 (pre-rope)
__device__ float g_cos[64];
__device__ float g_sin[64];
__device__ float g_l[NH * NSPLIT];
__device__ __align__(16) float g_acc[NH * NSPLIT * HD];
__device__ __align__(16) float g_ctx[NH * HD];
__device__ unsigned g_c0, g_c1, g_c2, g_c3;

__device__ __forceinline__ float warpsum(float v) {
#pragma unroll
    for (int o = 16; o; o >>= 1) v += __shfl_xor_sync(0xffffffffu, v, o);
    return v;
}
__device__ __forceinline__ void arrive_release(unsigned* ctr) {
    asm volatile("red.release.gpu.global.add.u32 [%0], %1;" :: "l"(ctr), "r"(1u) : "memory");
}
__device__ __forceinline__ void wait_acquire(unsigned* ctr, unsigned target) {
    unsigned v;
    do {
        asm volatile("ld.acquire.gpu.global.u32 %0, [%1];" : "=r"(v) : "l"(ctr) : "memory");
        if (v >= target) break;
        __nanosleep(32);
    } while (true);
}
__device__ __forceinline__ void cpa16(void* smem_dst, const void* gsrc) {
    unsigned d = (unsigned)__cvta_generic_to_shared(smem_dst);
    asm volatile("cp.async.cg.shared.global [%0], [%1], 16;" :: "r"(d), "l"(gsrc));
}
__device__ __forceinline__ unsigned s2u(const void* p) {
    return (unsigned)__cvta_generic_to_shared(p);
}
__device__ __forceinline__ void mbar_init(unsigned mbar, unsigned cnt) {
    asm volatile("mbarrier.init.shared.b64 [%0], %1;" :: "r"(mbar), "r"(cnt) : "memory");
}
__device__ __forceinline__ void mbar_expect_tx(unsigned mbar, unsigned bytes) {
    asm volatile("mbarrier.arrive.expect_tx.shared.b64 _, [%0], %1;" :: "r"(mbar), "r"(bytes) : "memory");
}
__device__ __forceinline__ void bulk_g2s(unsigned sdst, const void* gsrc, unsigned bytes, unsigned mbar) {
    asm volatile("cp.async.bulk.shared::cta.global.mbarrier::complete_tx::bytes [%0], [%1], %2, [%3];"
                 :: "r"(sdst), "l"(gsrc), "r"(bytes), "r"(mbar) : "memory");
}
__device__ __forceinline__ void l2_prefetch(const void* gsrc, unsigned bytes) {
    asm volatile("cp.async.bulk.prefetch.L2.global [%0], %1;" :: "l"(gsrc), "r"(bytes) : "memory");
}
__device__ __forceinline__ void mbar_wait(unsigned mbar, unsigned parity) {
    unsigned done;
    asm volatile("{\n\t.reg .pred p;\n\t"
                 "mbarrier.try_wait.parity.acquire.cta.shared::cta.b64 p, [%1], %2;\n\t"
                 "selp.b32 %0, 1, 0, p;\n\t}"
                 : "=r"(done) : "r"(mbar), "r"(parity) : "memory");
    while (!done) {
        __nanosleep(32);
        asm volatile("{\n\t.reg .pred p;\n\t"
                     "mbarrier.try_wait.parity.acquire.cta.shared::cta.b64 p, [%1], %2;\n\t"
                     "selp.b32 %0, 1, 0, p;\n\t}"
                     : "=r"(done) : "r"(mbar), "r"(parity) : "memory");
    }
}

// ====== single kernel; L2-prefetch front, dual-path demand fills ===============
__global__ void __launch_bounds__(NTHR, 2) k_mega(const int* __restrict__ ids,
                                                  const int* __restrict__ pos_ids,
                                                  const float* __restrict__ embed_w,
                                                  const float* __restrict__ ln_w,
                                                  const float* __restrict__ qw, const float* __restrict__ qb,
                                                  const float* __restrict__ kw, const float* __restrict__ kb,
                                                  const float* __restrict__ vw, const float* __restrict__ vb,
                                                  const float* __restrict__ ow,
                                                  const float* __restrict__ kv_cache,
                                                  float* __restrict__ out) {
    extern __shared__ float smem[];
    float* s_wA = smem + OFF_WA;
    float* s_wO = smem + OFF_WO;
    float* s_nc = smem + OFF_NC;
    float* s_kb = smem + OFF_KB;
    float* s_vb = smem + OFF_VB;

    __shared__ __align__(8) unsigned long long s_mbar[2];
    __shared__ float s_eh[16][GQA];
    __shared__ float s_red[18];
    __shared__ float s_pA[16];
    __shared__ float s_b[8];
    __shared__ float s_p[12];
    __shared__ int   s_last;

    const int tid = threadIdx.x, warp = tid >> 5, lane = tid & 31;
    const int bid = blockIdx.x;

    const int tok = ids[0];
    const int cp  = pos_ids[0];

    const int kvh = bid / NSPLIT;
    const int split = bid - kvh * NSPLIT;
    const int nk = cp + 1;
    const int chunk = (nk + NSPLIT - 1) / NSPLIT;   // 10 for cp=1234 (<= 16 assumed)
    const int t0 = split * chunk;
    const int t1 = min(t0 + chunk, nk);
    const int t = t0 + warp;
    const bool valid = t < t1;
    const bool fresh = (t == cp);

    // weight source base for this block's 8 qkv rows
    const float* srcA;
    if (bid < 192)      srcA = qw + (size_t)bid * 8 * H;
    else if (bid < 224) srcA = kw + (size_t)(bid - 192) * 8 * H;
    else                srcA = vw + (size_t)(bid - 224) * 8 * H;
    const float* srcO = ow + (size_t)bid * 6 * H;
    const float* kcf = kv_cache + (size_t)kvh * CTX * HD;
    const float* vcf = kv_cache + (size_t)NLAYERS * NKV * CTX * HD + (size_t)kvh * CTX * HD;

    // ---- L2 PREFETCH FRONT: fire-and-forget, no smem destination, no tracking ----
    //      If the ~1.4TB/s wall is an SM-destined in-flight cap, these bypass it and
    //      warm L2 so the demand fills below complete at L2-hit latency.
    if (tid == 0) {
        l2_prefetch(srcA,                 16384u);
        l2_prefetch(srcA + 4096,          16384u);
        l2_prefetch(srcA + 8192,          16384u);   // 48KB qkv tile
        l2_prefetch(srcO,                 12288u);
        l2_prefetch(srcO + 3072,          12288u);
        l2_prefetch(srcO + 6144,          12288u);   // 36KB oproj tile
        if (t1 > t0) {
            const unsigned kvb = (unsigned)(t1 - t0) * 512u;   // contiguous rows t0..t1
            l2_prefetch(kcf + (size_t)t0 * HD, kvb);
            l2_prefetch(vcf + (size_t)t0 * HD, kvb);
        }
    }

    // ---- mbarrier init (before any bulk issue) ----------------------------------
    if (tid == 0) { mbar_init(s2u(&s_mbar[0]), 1u); mbar_init(s2u(&s_mbar[1]), 1u); }

    // ---- group 0: qkv rows 0-3 via cp.async (24KB) -------------------------------
    {
        const float4* a4 = (const float4*)srcA;
#pragma unroll
        for (int i = 0; i < 3; i++)
            cpa16(&s_wA[(tid + i * 512) * 4], &a4[tid + i * 512]);
    }
    asm volatile("cp.async.commit_group;");

    // ---- group 1: KV (7KB; needed only at phase B) --------------------------------
    const float4* kc = (const float4*)kcf;
    const float4* vc = (const float4*)vcf;
    if (valid && !fresh) {
        cpa16(&s_kb[warp * 128 + lane * 4], &kc[t * 32 + lane]);
        cpa16(&s_vb[warp * 128 + lane * 4], &vc[t * 32 + lane]);
    }
    asm volatile("cp.async.commit_group;");

    // ---- group 2: oproj rows 0-2 (18KB; needed only at phase D) -------------------
    {
        const float4* o4 = (const float4*)srcO;
        cpa16(&s_wO[tid * 4], &o4[tid]);
        cpa16(&s_wO[(tid + 512) * 4], &o4[tid + 512]);
        if (tid < 128) cpa16(&s_wO[(tid + 1024) * 4], &o4[tid + 1024]);
    }
    asm volatile("cp.async.commit_group;");

    // ---- small LDGs ---------------------------------------------------------------
    const float4* er  = (const float4*)(embed_w + (size_t)tok * H);
    const float4* lw4 = (const float4*)ln_w;
    float4 e0 = make_float4(0.f,0.f,0.f,0.f), l0 = e0;
    if (tid < 384) { e0 = er[tid]; l0 = lw4[tid]; }
    float resid = 0.f;
    if (tid < 6) resid = embed_w[(size_t)tok * H + bid * 6 + tid];
    if (tid < 8) {
        const int r = bid * 8 + tid;
        s_b[tid] = (r < H) ? qb[r] : ((r < H + NKV*HD) ? kb[r - H] : vb[r - H - NKV*HD]);
    }

    __syncthreads();   // mbar init visible before bulk issue

    // ---- TMA-path stream: qkv rows 4-7 (2x12KB) then oproj rows 3-5 (2x9KB) -------
    if (tid == 0) {
        mbar_expect_tx(s2u(&s_mbar[0]), 24576u);
        bulk_g2s(s2u(s_wA + 4 * H), srcA + 4 * H, 12288u, s2u(&s_mbar[0]));
        bulk_g2s(s2u(s_wA + 6 * H), srcA + 6 * H, 12288u, s2u(&s_mbar[0]));
        mbar_expect_tx(s2u(&s_mbar[1]), 18432u);
        bulk_g2s(s2u(s_wO + 3 * H), srcO + 3 * H, 9216u, s2u(&s_mbar[1]));
        bulk_g2s(s2u(s_wO + 4 * H + H / 2), srcO + 4 * H + H / 2, 9216u, s2u(&s_mbar[1]));
    }

    // rope tables (block 0; overlapped with streams)
    if (bid == 0 && tid < 64) {
        const double p = (double)cp;
        const double invf = exp2(-(double)tid * (19.931568569324174 / 64.0)); // 1e6^(-i/64)
        const double ang = p * invf;
        g_cos[tid] = (float)cos(ang);
        g_sin[tid] = (float)sin(ang);
    }

    // =========== phase A: RMSNorm + QKV matvec (from dual-path smem) =============
    {
        float ss = e0.x * e0.x + e0.y * e0.y + e0.z * e0.z + e0.w * e0.w;  // 0 for tid>=384
        ss = warpsum(ss);
        if (lane == 0) s_red[warp] = ss;
        __syncthreads();
        if (tid == 0) {
            float v = 0.f;
#pragma unroll
            for (int i = 0; i < 16; i++) v += s_red[i];
            s_red[16] = rsqrtf(v / (float)H + 1e-6f);
        }
        __syncthreads();
        const float inv = s_red[16];
        if (tid < 384)
            ((float4*)s_nc)[tid] = make_float4(e0.x * inv * l0.x, e0.y * inv * l0.y,
                                               e0.z * inv * l0.z, e0.w * inv * l0.w);

        // qkv tile resident: cp.async half (g0 only) + TMA half
        asm volatile("cp.async.wait_group 2;");
        mbar_wait(s2u(&s_mbar[0]), 0u);
        __syncthreads();

        const int rowL = warp >> 1;          // 0..7
        const int half = warp & 1;
        const float4* wrow = (const float4*)(s_wA + rowL * H) + half * 192;
        const float4* nv   = (const float4*)s_nc + half * 192;
        float acc = 0.f;
#pragma unroll
        for (int i = 0; i < 6; i++) {
            const float4 wv = wrow[lane + i * 32];
            const float4 n4 = nv[lane + i * 32];
            acc += wv.x * n4.x + wv.y * n4.y + wv.z * n4.z + wv.w * n4.w;
        }
        acc = warpsum(acc);
        if (lane == 0) s_pA[warp] = acc;
        __syncthreads();
        if (tid < 8) g_qkv[bid * 8 + tid] = s_pA[2 * tid] + s_pA[2 * tid + 1] + s_b[tid];
        __syncthreads();
    }
    if (tid == 0) arrive_release(&g_c0);

    // =========== phase B: attention split (no-shift softmax) ======================
    if (tid == 0) wait_acquire(&g_c0, NBLK);
    asm volatile("cp.async.wait_group 1;");      // KV resident (oproj may pend)
    __syncthreads();

    float c4[4], s4[4];
#pragma unroll
    for (int j = 0; j < 4; j++) {
        const int i = (4 * lane + j) & 63;
        c4[j] = g_cos[i];
        s4[j] = g_sin[i];
    }
    const float sgn = (lane < 16) ? -1.f : 1.f;

    const float4* q4p = (const float4*)g_qkv;
    float4 q[GQA];
#pragma unroll
    for (int h = 0; h < GQA; h++) {
        const float4 x = q4p[(kvh * GQA + h) * 32 + lane];
        const float px = __shfl_xor_sync(0xffffffffu, x.x, 16);
        const float py = __shfl_xor_sync(0xffffffffu, x.y, 16);
        const float pz = __shfl_xor_sync(0xffffffffu, x.z, 16);
        const float pw = __shfl_xor_sync(0xffffffffu, x.w, 16);
        q[h].x = x.x * c4[0] + sgn * px * s4[0];
        q[h].y = x.y * c4[1] + sgn * py * s4[1];
        q[h].z = x.z * c4[2] + sgn * pz * s4[2];
        q[h].w = x.w * c4[3] + sgn * pw * s4[3];
    }

    float4 kcur = make_float4(0.f, 0.f, 0.f, 0.f);
    float4 vcur = make_float4(0.f, 0.f, 0.f, 0.f);
    if (valid) {
        if (fresh) {
            const float4 x = q4p[H / 4 + kvh * 32 + lane];
            const float px = __shfl_xor_sync(0xffffffffu, x.x, 16);
            const float py = __shfl_xor_sync(0xffffffffu, x.y, 16);
            const float pz = __shfl_xor_sync(0xffffffffu, x.z, 16);
            const float pw = __shfl_xor_sync(0xffffffffu, x.w, 16);
            kcur.x = x.x * c4[0] + sgn * px * s4[0];
            kcur.y = x.y * c4[1] + sgn * py * s4[1];
            kcur.z = x.z * c4[2] + sgn * pz * s4[2];
            kcur.w = x.w * c4[3] + sgn * pw * s4[3];
            vcur = q4p[(H + NKV * HD) / 4 + kvh * 32 + lane];
        } else {
            kcur = ((const float4*)(s_kb + warp * 128))[lane];
            vcur = ((const float4*)(s_vb + warp * 128))[lane];
        }
    }

#pragma unroll
    for (int h = 0; h < GQA; h++) {
        float d = q[h].x * kcur.x + q[h].y * kcur.y + q[h].z * kcur.z + q[h].w * kcur.w;
        d = warpsum(d) * 0.08838834764831845f;   // 1/sqrt(128)
        if (lane == 0) s_eh[warp][h] = valid ? __expf(fminf(d, 80.f)) : 0.f;
    }
    ((float4*)(s_vb + warp * 128))[lane] = vcur;   // canonical V (incl zeros/fresh)
    __syncthreads();

    if (warp < GQA) {
        const int h = warp;
        float bl = 0.f;
        float4 ba = make_float4(0.f, 0.f, 0.f, 0.f);
#pragma unroll
        for (int w = 0; w < 16; w++) {
            const float e = s_eh[w][h];
            bl += e;
            const float4 vw4 = ((const float4*)(s_vb + w * 128))[lane];
            ba.x += vw4.x * e; ba.y += vw4.y * e; ba.z += vw4.z * e; ba.w += vw4.w * e;
        }
        const int qh = kvh * GQA + h;
        if (lane == 0) g_l[qh * NSPLIT + split] = bl;
        ((float4*)g_acc)[(qh * NSPLIT + split) * 32 + lane] = ba;
    }
    __syncthreads();
    if (tid == 0) arrive_release(&g_c1);

    // =========== phase C: combine (blocks 0..11; head = bid) — PROVEN PATH ========
    if (bid < NH) {
        if (tid == 0) wait_acquire(&g_c1, NBLK);
        __syncthreads();
        const int qh = bid;
        float lv = (tid < NSPLIT) ? g_l[qh * NSPLIT + tid] : 0.f;
        lv = warpsum(lv);
        if (lane == 0) s_red[warp] = lv;
        __syncthreads();
        if (tid == 0) {
            float L = 0.f;
#pragma unroll
            for (int i = 0; i < 4; i++) L += s_red[i];
            s_red[17] = 1.f / L;
        }
        __syncthreads();

        // 4 threads per dim, 32 splits each (fully unrolled -> deep L2 MLP)
        float* s_part = s_kb;                      // KV buffer is free now
        const int d = tid & 127;
        const int qq = tid >> 7;                   // 0..3
        const float* accp = g_acc + (size_t)qh * NSPLIT * HD + (size_t)qq * 32 * HD + d;
        float s = 0.f;
#pragma unroll
        for (int sp = 0; sp < 32; sp++) s += __ldg(&accp[sp * HD]);
        s_part[tid] = s;
        __syncthreads();
        if (tid < HD)
            g_ctx[qh * HD + tid] = (s_part[tid] + s_part[tid + 128] + s_part[tid + 256] + s_part[tid + 384]) * s_red[17];
        __syncthreads();
        if (tid == 0) arrive_release(&g_c2);
    }

    // =========== phase D: oproj (dual-path smem) + residual =======================
    if (tid == 0) {
        wait_acquire(&g_c2, NH);
        const unsigned old = atomicAdd(&g_c3, 1u);
        s_last = (old == NBLK - 1u) ? 1 : 0;
    }
    __syncthreads();
    if (s_last && tid == 0) {
        *(volatile unsigned*)&g_c0 = 0u;
        *(volatile unsigned*)&g_c1 = 0u;
        *(volatile unsigned*)&g_c2 = 0u;
        *(volatile unsigned*)&g_c3 = 0u;
    }

    if (tid < 384) ((float4*)s_nc)[tid] = ((const float4*)g_ctx)[tid];
    asm volatile("cp.async.wait_group 0;");       // oproj cp.async half
    mbar_wait(s2u(&s_mbar[1]), 0u);               // oproj TMA half
    __syncthreads();

    if (warp < 12) {
        const int rowL = warp >> 1;                // 0..5
        const int half = warp & 1;
        const float4* wrow = (const float4*)(s_wO + rowL * H) + half * 192;
        const float4* cv   = (const float4*)s_nc + half * 192;
        float acc = 0.f;
#pragma unroll
        for (int i = 0; i < 6; i++) {
            const float4 wv = wrow[lane + i * 32];
            const float4 c = cv[lane + i * 32];
            acc += wv.x * c.x + wv.y * c.y + wv.z * c.z + wv.w * c.w;
        }
        acc = warpsum(acc);
        if (lane == 0) s_p[warp] = acc;
    }
    __syncthreads();
    if (tid < 6) out[bid * 6 + tid] = resid + s_p[2 * tid] + s_p[2 * tid + 1];
}

// ---------------- launch --------------------------------------------------------
extern "C" void kernel_launch(void* const* d_in, const int* in_sizes, int n_in,
                              void* d_out, int out_size) {
    const int*   ids     = (const int*)d_in[0];
    const int*   pos_ids = (const int*)d_in[1];
    const float* embed_w = (const float*)d_in[4];
    const float* ln_w    = (const float*)d_in[5];
    const float* qw      = (const float*)d_in[6];
    const float* qb      = (const float*)d_in[7];
    const float* kw      = (const float*)d_in[8];
    const float* kb      = (const float*)d_in[9];
    const float* vw      = (const float*)d_in[10];
    const float* vb      = (const float*)d_in[11];
    const float* ow      = (const float*)d_in[12];
    const float* kvc     = (const float*)d_in[13];
    float* out = (float*)d_out;

    static int attr_set = 0;
    if (!attr_set) {
        cudaFuncSetAttribute(k_mega, cudaFuncAttributeMaxDynamicSharedMemorySize,
                             SMEM_FLOATS * sizeof(float));
        attr_set = 1;
    }
    k_mega<<<NBLK, NTHR, SMEM_FLOATS * sizeof(float)>>>(ids, pos_ids, embed_w, ln_w,
                                                        qw, qb, kw, kb, vw, vb, ow, kvc, out);
}

// round 16
// speedup vs baseline: 1.0878x; 1.0878x over previous
#include <cuda_runtime.h>

#define H       1536
#define NH      12
#define NKV     2
#define GQA     6
#define HD      128
#define CTX     4096
#define NLAYERS 28
#define NSPLIT  128
#define NBLK    256      // 2 CTAs/SM * 148 = 296 >= 256 -> co-resident
#define NTHR    512

// smem float offsets
#define OFF_WA  0        // 12288 floats (8 qkv rows: 0-3 cp.async, 4-7 bulk)
#define OFF_WO  12288    // 9216 floats (6 oproj rows: 0-2 cp.async, 3-5 bulk)
#define OFF_NC  21504    // 1536 floats (norm vec / ctx)
#define OFF_KB  23040    // 2048 floats (16 warps x 128 K)
#define OFF_VB  25088    // 2048 floats (16 warps x 128 V)
#define SMEM_FLOATS 27136   // 108544 bytes

// ---------------- device globals (zero-init; counters self-reset) --------------
__device__ __align__(16) float g_qkv[2048];   // q:0..1535, k:1536..1791, v:1792..2047 (pre-rope)
__device__ float g_cos[64];
__device__ float g_sin[64];
__device__ float g_l[NH * NSPLIT];
__device__ __align__(16) float g_acc[NH * NSPLIT * HD];
__device__ __align__(16) float g_ctx[NH * HD];
__device__ unsigned g_c0, g_c1, g_c2, g_c3;

__device__ __forceinline__ float warpsum(float v) {
#pragma unroll
    for (int o = 16; o; o >>= 1) v += __shfl_xor_sync(0xffffffffu, v, o);
    return v;
}
__device__ __forceinline__ void arrive_release(unsigned* ctr) {
    asm volatile("red.release.gpu.global.add.u32 [%0], %1;" :: "l"(ctr), "r"(1u) : "memory");
}
__device__ __forceinline__ void wait_acquire(unsigned* ctr, unsigned target) {
    unsigned v;
    do {
        asm volatile("ld.acquire.gpu.global.u32 %0, [%1];" : "=r"(v) : "l"(ctr) : "memory");
        if (v >= target) break;
        __nanosleep(32);
    } while (true);
}
__device__ __forceinline__ void cpa16(void* smem_dst, const void* gsrc) {
    unsigned d = (unsigned)__cvta_generic_to_shared(smem_dst);
    asm volatile("cp.async.cg.shared.global [%0], [%1], 16;" :: "r"(d), "l"(gsrc));
}
__device__ __forceinline__ unsigned s2u(const void* p) {
    return (unsigned)__cvta_generic_to_shared(p);
}
__device__ __forceinline__ void mbar_init(unsigned mbar, unsigned cnt) {
    asm volatile("mbarrier.init.shared.b64 [%0], %1;" :: "r"(mbar), "r"(cnt) : "memory");
}
__device__ __forceinline__ void mbar_expect_tx(unsigned mbar, unsigned bytes) {
    asm volatile("mbarrier.arrive.expect_tx.shared.b64 _, [%0], %1;" :: "r"(mbar), "r"(bytes) : "memory");
}
__device__ __forceinline__ void bulk_g2s(unsigned sdst, const void* gsrc, unsigned bytes, unsigned mbar) {
    asm volatile("cp.async.bulk.shared::cta.global.mbarrier::complete_tx::bytes [%0], [%1], %2, [%3];"
                 :: "r"(sdst), "l"(gsrc), "r"(bytes), "r"(mbar) : "memory");
}
__device__ __forceinline__ void mbar_wait(unsigned mbar, unsigned parity) {
    unsigned done;
    asm volatile("{\n\t.reg .pred p;\n\t"
                 "mbarrier.try_wait.parity.acquire.cta.shared::cta.b64 p, [%1], %2;\n\t"
                 "selp.b32 %0, 1, 0, p;\n\t}"
                 : "=r"(done) : "r"(mbar), "r"(parity) : "memory");
    while (!done) {
        __nanosleep(32);
        asm volatile("{\n\t.reg .pred p;\n\t"
                     "mbarrier.try_wait.parity.acquire.cta.shared::cta.b64 p, [%1], %2;\n\t"
                     "selp.b32 %0, 1, 0, p;\n\t}"
                     : "=r"(done) : "r"(mbar), "r"(parity) : "memory");
    }
}

// ====== single kernel; PRIORITIZED streams: qkv+KV first, oproj after c0 =======
__global__ void __launch_bounds__(NTHR, 2) k_mega(const int* __restrict__ ids,
                                                  const int* __restrict__ pos_ids,
                                                  const float* __restrict__ embed_w,
                                                  const float* __restrict__ ln_w,
                                                  const float* __restrict__ qw, const float* __restrict__ qb,
                                                  const float* __restrict__ kw, const float* __restrict__ kb,
                                                  const float* __restrict__ vw, const float* __restrict__ vb,
                                                  const float* __restrict__ ow,
                                                  const float* __restrict__ kv_cache,
                                                  float* __restrict__ out) {
    extern __shared__ float smem[];
    float* s_wA = smem + OFF_WA;
    float* s_wO = smem + OFF_WO;
    float* s_nc = smem + OFF_NC;
    float* s_kb = smem + OFF_KB;
    float* s_vb = smem + OFF_VB;

    __shared__ __align__(8) unsigned long long s_mbar[2];
    __shared__ float s_eh[16][GQA];
    __shared__ float s_red[18];
    __shared__ float s_pA[16];
    __shared__ float s_b[8];
    __shared__ float s_p[12];
    __shared__ int   s_last;

    const int tid = threadIdx.x, warp = tid >> 5, lane = tid & 31;
    const int bid = blockIdx.x;

    const int tok = ids[0];
    const int cp  = pos_ids[0];

    const int kvh = bid / NSPLIT;
    const int split = bid - kvh * NSPLIT;
    const int nk = cp + 1;
    const int chunk = (nk + NSPLIT - 1) / NSPLIT;   // 10 for cp=1234 (<= 16 assumed)
    const int t0 = split * chunk;
    const int t1 = min(t0 + chunk, nk);
    const int t = t0 + warp;
    const bool valid = t < t1;
    const bool fresh = (t == cp);

    // weight source base for this block's 8 qkv rows
    const float* srcA;
    if (bid < 192)      srcA = qw + (size_t)bid * 8 * H;
    else if (bid < 224) srcA = kw + (size_t)(bid - 192) * 8 * H;
    else                srcA = vw + (size_t)(bid - 224) * 8 * H;
    const float* srcO = ow + (size_t)bid * 6 * H;

    // ---- mbarrier init (before any bulk issue) ----------------------------------
    if (tid == 0) { mbar_init(s2u(&s_mbar[0]), 1u); mbar_init(s2u(&s_mbar[1]), 1u); }

    // ---- group 0: qkv rows 0-3 via cp.async (24KB) — critical path ---------------
    {
        const float4* a4 = (const float4*)srcA;
#pragma unroll
        for (int i = 0; i < 3; i++)
            cpa16(&s_wA[(tid + i * 512) * 4], &a4[tid + i * 512]);
    }
    asm volatile("cp.async.commit_group;");

    // ---- group 1: KV (7KB; needed at phase B) --------------------------------------
    const float4* kc = (const float4*)(kv_cache + (size_t)kvh * CTX * HD);
    const float4* vc = (const float4*)(kv_cache + (size_t)NLAYERS * NKV * CTX * HD + (size_t)kvh * CTX * HD);
    if (valid && !fresh) {
        cpa16(&s_kb[warp * 128 + lane * 4], &kc[t * 32 + lane]);
        cpa16(&s_vb[warp * 128 + lane * 4], &vc[t * 32 + lane]);
    }
    asm volatile("cp.async.commit_group;");

    // NOTE: oproj stream intentionally NOT issued here — it would fair-share the
    // pipe and push the qkv stream's completion (and thus c0) to the end of the
    // whole 24MB window. It is issued after the c0 wait in phase B instead.

    // ---- small LDGs ---------------------------------------------------------------
    const float4* er  = (const float4*)(embed_w + (size_t)tok * H);
    const float4* lw4 = (const float4*)ln_w;
    float4 e0 = make_float4(0.f,0.f,0.f,0.f), l0 = e0;
    if (tid < 384) { e0 = er[tid]; l0 = lw4[tid]; }
    float resid = 0.f;
    if (tid < 6) resid = embed_w[(size_t)tok * H + bid * 6 + tid];
    if (tid < 8) {
        const int r = bid * 8 + tid;
        s_b[tid] = (r < H) ? qb[r] : ((r < H + NKV*HD) ? kb[r - H] : vb[r - H - NKV*HD]);
    }

    __syncthreads();   // mbar init visible before bulk issue

    // ---- TMA-path stream: qkv rows 4-7 (2x12KB) ONLY (oproj deferred) -------------
    if (tid == 0) {
        mbar_expect_tx(s2u(&s_mbar[0]), 24576u);
        bulk_g2s(s2u(s_wA + 4 * H), srcA + 4 * H, 12288u, s2u(&s_mbar[0]));
        bulk_g2s(s2u(s_wA + 6 * H), srcA + 6 * H, 12288u, s2u(&s_mbar[0]));
    }

    // rope tables (block 0; overlapped with streams)
    if (bid == 0 && tid < 64) {
        const double p = (double)cp;
        const double invf = exp2(-(double)tid * (19.931568569324174 / 64.0)); // 1e6^(-i/64)
        const double ang = p * invf;
        g_cos[tid] = (float)cos(ang);
        g_sin[tid] = (float)sin(ang);
    }

    // =========== phase A: RMSNorm + QKV matvec (from dual-path smem) =============
    {
        float ss = e0.x * e0.x + e0.y * e0.y + e0.z * e0.z + e0.w * e0.w;  // 0 for tid>=384
        ss = warpsum(ss);
        if (lane == 0) s_red[warp] = ss;
        __syncthreads();
        if (tid == 0) {
            float v = 0.f;
#pragma unroll
            for (int i = 0; i < 16; i++) v += s_red[i];
            s_red[16] = rsqrtf(v / (float)H + 1e-6f);
        }
        __syncthreads();
        const float inv = s_red[16];
        if (tid < 384)
            ((float4*)s_nc)[tid] = make_float4(e0.x * inv * l0.x, e0.y * inv * l0.y,
                                               e0.z * inv * l0.z, e0.w * inv * l0.w);

        // qkv tile resident: cp.async half (g0) + TMA half (g1=KV may still pend)
        asm volatile("cp.async.wait_group 1;");
        mbar_wait(s2u(&s_mbar[0]), 0u);
        __syncthreads();

        const int rowL = warp >> 1;          // 0..7
        const int half = warp & 1;
        const float4* wrow = (const float4*)(s_wA + rowL * H) + half * 192;
        const float4* nv   = (const float4*)s_nc + half * 192;
        float acc = 0.f;
#pragma unroll
        for (int i = 0; i < 6; i++) {
            const float4 wv = wrow[lane + i * 32];
            const float4 n4 = nv[lane + i * 32];
            acc += wv.x * n4.x + wv.y * n4.y + wv.z * n4.z + wv.w * n4.w;
        }
        acc = warpsum(acc);
        if (lane == 0) s_pA[warp] = acc;
        __syncthreads();
        if (tid < 8) g_qkv[bid * 8 + tid] = s_pA[2 * tid] + s_pA[2 * tid + 1] + s_b[tid];
        __syncthreads();
    }
    if (tid == 0) arrive_release(&g_c0);

    // =========== phase B: attention split; oproj stream launched HERE =============
    if (tid == 0) wait_acquire(&g_c0, NBLK);
    asm volatile("cp.async.wait_group 0;");      // KV resident (g0,g1 both done)
    __syncthreads();

    // ---- oproj stream (group 2 + mbar1 bulk): now owns the pipe exclusively ------
    {
        const float4* o4 = (const float4*)srcO;
        cpa16(&s_wO[tid * 4], &o4[tid]);
        cpa16(&s_wO[(tid + 512) * 4], &o4[tid + 512]);
        if (tid < 128) cpa16(&s_wO[(tid + 1024) * 4], &o4[tid + 1024]);
    }
    asm volatile("cp.async.commit_group;");
    if (tid == 0) {
        mbar_expect_tx(s2u(&s_mbar[1]), 18432u);
        bulk_g2s(s2u(s_wO + 3 * H), srcO + 3 * H, 9216u, s2u(&s_mbar[1]));
        bulk_g2s(s2u(s_wO + 4 * H + H / 2), srcO + 4 * H + H / 2, 9216u, s2u(&s_mbar[1]));
    }

    float c4[4], s4[4];
#pragma unroll
    for (int j = 0; j < 4; j++) {
        const int i = (4 * lane + j) & 63;
        c4[j] = g_cos[i];
        s4[j] = g_sin[i];
    }
    const float sgn = (lane < 16) ? -1.f : 1.f;

    const float4* q4p = (const float4*)g_qkv;
    float4 q[GQA];
#pragma unroll
    for (int h = 0; h < GQA; h++) {
        const float4 x = q4p[(kvh * GQA + h) * 32 + lane];
        const float px = __shfl_xor_sync(0xffffffffu, x.x, 16);
        const float py = __shfl_xor_sync(0xffffffffu, x.y, 16);
        const float pz = __shfl_xor_sync(0xffffffffu, x.z, 16);
        const float pw = __shfl_xor_sync(0xffffffffu, x.w, 16);
        q[h].x = x.x * c4[0] + sgn * px * s4[0];
        q[h].y = x.y * c4[1] + sgn * py * s4[1];
        q[h].z = x.z * c4[2] + sgn * pz * s4[2];
        q[h].w = x.w * c4[3] + sgn * pw * s4[3];
    }

    float4 kcur = make_float4(0.f, 0.f, 0.f, 0.f);
    float4 vcur = make_float4(0.f, 0.f, 0.f, 0.f);
    if (valid) {
        if (fresh) {
            const float4 x = q4p[H / 4 + kvh * 32 + lane];
            const float px = __shfl_xor_sync(0xffffffffu, x.x, 16);
            const float py = __shfl_xor_sync(0xffffffffu, x.y, 16);
            const float pz = __shfl_xor_sync(0xffffffffu, x.z, 16);
            const float pw = __shfl_xor_sync(0xffffffffu, x.w, 16);
            kcur.x = x.x * c4[0] + sgn * px * s4[0];
            kcur.y = x.y * c4[1] + sgn * py * s4[1];
            kcur.z = x.z * c4[2] + sgn * pz * s4[2];
            kcur.w = x.w * c4[3] + sgn * pw * s4[3];
            vcur = q4p[(H + NKV * HD) / 4 + kvh * 32 + lane];
        } else {
            kcur = ((const float4*)(s_kb + warp * 128))[lane];
            vcur = ((const float4*)(s_vb + warp * 128))[lane];
        }
    }

#pragma unroll
    for (int h = 0; h < GQA; h++) {
        float d = q[h].x * kcur.x + q[h].y * kcur.y + q[h].z * kcur.z + q[h].w * kcur.w;
        d = warpsum(d) * 0.08838834764831845f;   // 1/sqrt(128)
        if (lane == 0) s_eh[warp][h] = valid ? __expf(fminf(d, 80.f)) : 0.f;
    }
    ((float4*)(s_vb + warp * 128))[lane] = vcur;   // canonical V (incl zeros/fresh)
    __syncthreads();

    if (warp < GQA) {
        const int h = warp;
        float bl = 0.f;
        float4 ba = make_float4(0.f, 0.f, 0.f, 0.f);
#pragma unroll
        for (int w = 0; w < 16; w++) {
            const float e = s_eh[w][h];
            bl += e;
            const float4 vw4 = ((const float4*)(s_vb + w * 128))[lane];
            ba.x += vw4.x * e; ba.y += vw4.y * e; ba.z += vw4.z * e; ba.w += vw4.w * e;
        }
        const int qh = kvh * GQA + h;
        if (lane == 0) g_l[qh * NSPLIT + split] = bl;
        ((float4*)g_acc)[(qh * NSPLIT + split) * 32 + lane] = ba;
    }
    __syncthreads();
    if (tid == 0) arrive_release(&g_c1);

    // =========== phase C: combine (blocks 0..11; head = bid) — PROVEN PATH ========
    if (bid < NH) {
        if (tid == 0) wait_acquire(&g_c1, NBLK);
        __syncthreads();
        const int qh = bid;
        float lv = (tid < NSPLIT) ? g_l[qh * NSPLIT + tid] : 0.f;
        lv = warpsum(lv);
        if (lane == 0) s_red[warp] = lv;
        __syncthreads();
        if (tid == 0) {
            float L = 0.f;
#pragma unroll
            for (int i = 0; i < 4; i++) L += s_red[i];
            s_red[17] = 1.f / L;
        }
        __syncthreads();

        // 4 threads per dim, 32 splits each (fully unrolled -> deep L2 MLP)
        float* s_part = s_kb;                      // KV buffer is free now
        const int d = tid & 127;
        const int qq = tid >> 7;                   // 0..3
        const float* accp = g_acc + (size_t)qh * NSPLIT * HD + (size_t)qq * 32 * HD + d;
        float s = 0.f;
#pragma unroll
        for (int sp = 0; sp < 32; sp++) s += __ldg(&accp[sp * HD]);
        s_part[tid] = s;
        __syncthreads();
        if (tid < HD)
            g_ctx[qh * HD + tid] = (s_part[tid] + s_part[tid + 128] + s_part[tid + 256] + s_part[tid + 384]) * s_red[17];
        __syncthreads();
        if (tid == 0) arrive_release(&g_c2);
    }

    // =========== phase D: oproj (dual-path smem) + residual =======================
    if (tid == 0) {
        wait_acquire(&g_c2, NH);
        const unsigned old = atomicAdd(&g_c3, 1u);
        s_last = (old == NBLK - 1u) ? 1 : 0;
    }
    __syncthreads();
    if (s_last && tid == 0) {
        *(volatile unsigned*)&g_c0 = 0u;
        *(volatile unsigned*)&g_c1 = 0u;
        *(volatile unsigned*)&g_c2 = 0u;
        *(volatile unsigned*)&g_c3 = 0u;
    }

    if (tid < 384) ((float4*)s_nc)[tid] = ((const float4*)g_ctx)[tid];
    asm volatile("cp.async.wait_group 0;");       // oproj cp.async half
    mbar_wait(s2u(&s_mbar[1]), 0u);               // oproj TMA half
    __syncthreads();

    if (warp < 12) {
        const int rowL = warp >> 1;                // 0..5
        const int half = warp & 1;
        const float4* wrow = (const float4*)(s_wO + rowL * H) + half * 192;
        const float4* cv   = (const float4*)s_nc + half * 192;
        float acc = 0.f;
#pragma unroll
        for (int i = 0; i < 6; i++) {
            const float4 wv = wrow[lane + i * 32];
            const float4 c = cv[lane + i * 32];
            acc += wv.x * c.x + wv.y * c.y + wv.z * c.z + wv.w * c.w;
        }
        acc = warpsum(acc);
        if (lane == 0) s_p[warp] = acc;
    }
    __syncthreads();
    if (tid < 6) out[bid * 6 + tid] = resid + s_p[2 * tid] + s_p[2 * tid + 1];
}

// ---------------- launch --------------------------------------------------------
extern "C" void kernel_launch(void* const* d_in, const int* in_sizes, int n_in,
                              void* d_out, int out_size) {
    const int*   ids     = (const int*)d_in[0];
    const int*   pos_ids = (const int*)d_in[1];
    const float* embed_w = (const float*)d_in[4];
    const float* ln_w    = (const float*)d_in[5];
    const float* qw      = (const float*)d_in[6];
    const float* qb      = (const float*)d_in[7];
    const float* kw      = (const float*)d_in[8];
    const float* kb      = (const float*)d_in[9];
    const float* vw      = (const float*)d_in[10];
    const float* vb      = (const float*)d_in[11];
    const float* ow      = (const float*)d_in[12];
    const float* kvc     = (const float*)d_in[13];
    float* out = (float*)d_out;

    static int attr_set = 0;
    if (!attr_set) {
        cudaFuncSetAttribute(k_mega, cudaFuncAttributeMaxDynamicSharedMemorySize,
                             SMEM_FLOATS * sizeof(float));
        attr_set = 1;
    }
    k_mega<<<NBLK, NTHR, SMEM_FLOATS * sizeof(float)>>>(ids, pos_ids, embed_w, ln_w,
                                                        qw, qb, kw, kb, vw, vb, ow, kvc, out);
}